// round 5
// baseline (speedup 1.0000x reference)
#include <cuda_runtime.h>
#include <math.h>
#include <stdint.h>

#define BATCH 32
#define SEQ   8192
#define HID   512
#define CHUNKS 37                     // per batch; 32*37 = 1184 total chunks
#define TOTCH (BATCH * CHUNKS)        // 1184
#define GRID  592                     // 148 SMs * 4 blocks = one full wave
#define NTHREADS 256
#define NWARPS   8

// Deterministic per-chunk partials + barrier counters (zero-init; self-reset).
__device__ float g_ctx_part[TOTCH * HID];    // ~2.4 MB scratch
__device__ float g_sum_part[TOTCH];
__device__ int   g_arrive;
__device__ int   g_depart;

// ---------------------------------------------------------------------------
// Single persistent kernel: 592 co-resident blocks, 2 chunks each, software
// grid barrier, then distributed in-kernel epilogue.
// ---------------------------------------------------------------------------
__global__ __launch_bounds__(NTHREADS, 4)
void attn_fused(const float* __restrict__ states_h,
                const float* __restrict__ enc_out,
                float* __restrict__ ctx_out,   // [BATCH*HID]
                float* __restrict__ w_out)     // [BATCH*SEQ]
{
    const int tid  = threadIdx.x;
    const int w    = tid >> 5;
    const int lane = tid & 31;

    __shared__ float4 s_ctx[NWARPS][HID / 4];   // 16 KB
    __shared__ float  s_sum[NWARPS];
    __shared__ float  s_inv;

    // ---------------- phase 1: stream enc_out (2 chunks per block) ---------
    for (int c = blockIdx.x; c < TOTCH; c += GRID) {
        const int b     = c / CHUNKS;
        const int chunk = c % CHUNKS;
        const int s_begin = (chunk * SEQ) / CHUNKS;
        const int s_end   = ((chunk + 1) * SEQ) / CHUNKS;

        float4 sh[4];
        const float4* shp = reinterpret_cast<const float4*>(states_h + b * HID);
        #pragma unroll
        for (int i = 0; i < 4; i++) sh[i] = shp[i * 32 + lane];

        float4 ctx[4];
        #pragma unroll
        for (int i = 0; i < 4; i++) ctx[i] = make_float4(0.f, 0.f, 0.f, 0.f);
        float sum_e = 0.0f;

        const float* enc_b = enc_out + (size_t)b * SEQ * HID;

        #pragma unroll 2
        for (int s = s_begin + w; s < s_end; s += NWARPS) {
            const float4* row = reinterpret_cast<const float4*>(enc_b + (size_t)s * HID);
            float4 v[4];
            #pragma unroll
            for (int i = 0; i < 4; i++) v[i] = __ldcs(&row[i * 32 + lane]);

            float dot = 0.0f;
            #pragma unroll
            for (int i = 0; i < 4; i++) {
                dot += v[i].x * sh[i].x + v[i].y * sh[i].y
                     + v[i].z * sh[i].z + v[i].w * sh[i].w;
            }
            #pragma unroll
            for (int off = 16; off; off >>= 1)
                dot += __shfl_xor_sync(0xFFFFFFFFu, dot, off);

            const float e = __expf(dot * (1.0f / 512.0f));
            if (lane == 0) {
                w_out[(size_t)b * SEQ + s] = e;      // unnormalized
                sum_e += e;
            }
            #pragma unroll
            for (int i = 0; i < 4; i++) {
                ctx[i].x = fmaf(e, v[i].x, ctx[i].x);
                ctx[i].y = fmaf(e, v[i].y, ctx[i].y);
                ctx[i].z = fmaf(e, v[i].z, ctx[i].z);
                ctx[i].w = fmaf(e, v[i].w, ctx[i].w);
            }
        }

        // cross-warp reduce into block partials for this chunk
        #pragma unroll
        for (int i = 0; i < 4; i++) s_ctx[w][i * 32 + lane] = ctx[i];
        if (lane == 0) s_sum[w] = sum_e;
        __syncthreads();

        {
            const float2* sc = reinterpret_cast<const float2*>(&s_ctx[0][0]);
            const int stride2 = HID / 2;
            float2 acc = make_float2(0.f, 0.f);
            #pragma unroll
            for (int ww = 0; ww < NWARPS; ww++) {
                float2 t = sc[ww * stride2 + tid];
                acc.x += t.x; acc.y += t.y;
            }
            float2* dst = reinterpret_cast<float2*>(g_ctx_part + (size_t)c * HID);
            dst[tid] = acc;
        }
        if (tid == 0) {
            float t = 0.f;
            #pragma unroll
            for (int ww = 0; ww < NWARPS; ww++) t += s_sum[ww];
            g_sum_part[c] = t;
        }
        __syncthreads();   // protect s_ctx reuse next chunk
    }

    // ---------------- software grid barrier (all 592 blocks resident) ------
    if (tid == 0) {
        __threadfence();                 // cumulative: publishes block's writes
        atomicAdd(&g_arrive, 1);
        while (*(volatile int*)&g_arrive < GRID) { }
        __threadfence();                 // acquire side
    }
    __syncthreads();

    // ---------------- phase 2: distributed epilogue ------------------------
    const int bid = blockIdx.x;

    if (bid < 256) {
        // w-normalize: block covers 256 consecutive float4 = one batch slice
        const int b = bid >> 3;                 // 8 blocks per batch
        if (tid < 32) {
            const float* sp = g_sum_part + b * CHUNKS;
            float v = sp[tid];
            if (tid + 32 < CHUNKS) v += sp[tid + 32];
            #pragma unroll
            for (int off = 16; off; off >>= 1)
                v += __shfl_xor_sync(0xFFFFFFFFu, v, off);
            if (tid == 0) s_inv = __frcp_rn(v);
        }
        __syncthreads();
        const float inv = s_inv;

        float4* wp = reinterpret_cast<float4*>(w_out) + (size_t)bid * NTHREADS;
        float4 t = wp[tid];
        t.x *= inv; t.y *= inv; t.z *= inv; t.w *= inv;
        wp[tid] = t;
    } else if (bid < 256 + 2 * BATCH) {
        // ctx reduce: 2 blocks per batch, 256 h each
        const int t2 = bid - 256;
        const int b  = t2 >> 1;
        const int h  = (t2 & 1) * NTHREADS + tid;
        if (tid < 32) {
            const float* sp = g_sum_part + b * CHUNKS;
            float v = sp[tid];
            if (tid + 32 < CHUNKS) v += sp[tid + 32];
            #pragma unroll
            for (int off = 16; off; off >>= 1)
                v += __shfl_xor_sync(0xFFFFFFFFu, v, off);
            if (tid == 0) s_inv = __frcp_rn(v);
        }
        __syncthreads();
        const float inv = s_inv;

        float acc = 0.0f;
        #pragma unroll
        for (int c = 0; c < CHUNKS; c++)
            acc += g_ctx_part[((size_t)b * CHUNKS + c) * HID + h];
        ctx_out[b * HID + h] = acc * inv;
    }

    // ---------------- reset barrier for next graph replay ------------------
    __syncthreads();
    if (tid == 0) {
        int old = atomicAdd(&g_depart, 1);
        if (old == GRID - 1) {           // provably last block past the barrier
            g_arrive = 0;
            g_depart = 0;
        }
    }
}

// ---------------------------------------------------------------------------
extern "C" void kernel_launch(void* const* d_in, const int* in_sizes, int n_in,
                              void* d_out, int out_size)
{
    const float* states_h = nullptr;
    const float* enc_out  = nullptr;
    for (int i = 0; i < n_in; i++) {
        if (in_sizes[i] == BATCH * HID)            states_h = (const float*)d_in[i];
        else if ((int64_t)in_sizes[i] == (int64_t)BATCH * SEQ * HID)
                                                   enc_out  = (const float*)d_in[i];
    }

    float* ctx_out = (float*)d_out;                 // [context | weights]
    float* w_out   = (float*)d_out + BATCH * HID;

    attn_fused<<<GRID, NTHREADS>>>(states_h, enc_out, ctx_out, w_out);
}

// round 6
// speedup vs baseline: 1.0618x; 1.0618x over previous
#include <cuda_runtime.h>
#include <math.h>
#include <stdint.h>

#define BATCH 32
#define SEQ   8192
#define HID   512
#define CHUNKS 37                    // 32*37 = 1184 = 2 * (148 SMs * 4 blocks) exactly
#define NTHREADS 256
#define NWARPS   8

// Deterministic per-block partials (no atomics, no fences).
__device__ float g_ctx_part[BATCH * CHUNKS * HID];   // ~2.4 MB scratch
__device__ float g_sum_part[BATCH * CHUNKS];

// ---------------------------------------------------------------------------
// Kernel 1: fused single-pass — streams enc_out exactly once.
// grid = 1184 blocks = exactly 2 full waves at 4 blocks/SM.  (R4, unchanged)
// ---------------------------------------------------------------------------
__global__ __launch_bounds__(NTHREADS, 4)
void attn_main(const float* __restrict__ states_h,
               const float* __restrict__ enc_out,
               float* __restrict__ w_out)     // [BATCH*SEQ] unnormalized
{
    const int b     = blockIdx.x / CHUNKS;
    const int chunk = blockIdx.x % CHUNKS;
    const int tid   = threadIdx.x;
    const int w     = tid >> 5;
    const int lane  = tid & 31;

    const int s_begin = (chunk * SEQ) / CHUNKS;
    const int s_end   = ((chunk + 1) * SEQ) / CHUNKS;

    float4 sh[4];
    const float4* shp = reinterpret_cast<const float4*>(states_h + b * HID);
    #pragma unroll
    for (int i = 0; i < 4; i++) sh[i] = shp[i * 32 + lane];

    float4 ctx[4];
    #pragma unroll
    for (int i = 0; i < 4; i++) ctx[i] = make_float4(0.f, 0.f, 0.f, 0.f);
    float sum_e = 0.0f;

    const float* enc_b = enc_out + (size_t)b * SEQ * HID;

    #pragma unroll 2
    for (int s = s_begin + w; s < s_end; s += NWARPS) {
        const float4* row = reinterpret_cast<const float4*>(enc_b + (size_t)s * HID);
        float4 v[4];
        #pragma unroll
        for (int i = 0; i < 4; i++) v[i] = __ldcs(&row[i * 32 + lane]);

        float dot = 0.0f;
        #pragma unroll
        for (int i = 0; i < 4; i++) {
            dot += v[i].x * sh[i].x + v[i].y * sh[i].y
                 + v[i].z * sh[i].z + v[i].w * sh[i].w;
        }
        #pragma unroll
        for (int off = 16; off; off >>= 1)
            dot += __shfl_xor_sync(0xFFFFFFFFu, dot, off);

        const float e = __expf(dot * (1.0f / 512.0f));
        if (lane == 0) {
            w_out[(size_t)b * SEQ + s] = e;
            sum_e += e;
        }
        #pragma unroll
        for (int i = 0; i < 4; i++) {
            ctx[i].x = fmaf(e, v[i].x, ctx[i].x);
            ctx[i].y = fmaf(e, v[i].y, ctx[i].y);
            ctx[i].z = fmaf(e, v[i].z, ctx[i].z);
            ctx[i].w = fmaf(e, v[i].w, ctx[i].w);
        }
    }

    __shared__ float4 s_ctx[NWARPS][HID / 4];   // 16 KB
    __shared__ float  s_sum[NWARPS];
    #pragma unroll
    for (int i = 0; i < 4; i++) s_ctx[w][i * 32 + lane] = ctx[i];
    if (lane == 0) s_sum[w] = sum_e;
    __syncthreads();

    {
        const float2* sc = reinterpret_cast<const float2*>(&s_ctx[0][0]);
        const int stride2 = HID / 2;
        float2 acc = make_float2(0.f, 0.f);
        #pragma unroll
        for (int ww = 0; ww < NWARPS; ww++) {
            float2 t = sc[ww * stride2 + tid];
            acc.x += t.x; acc.y += t.y;
        }
        float2* dst = reinterpret_cast<float2*>(
            g_ctx_part + ((size_t)b * CHUNKS + chunk) * HID);
        dst[tid] = acc;
    }
    if (tid == 0) {
        float t = 0.f;
        #pragma unroll
        for (int ww = 0; ww < NWARPS; ww++) t += s_sum[ww];
        g_sum_part[b * CHUNKS + chunk] = t;
    }
}

// ---------------------------------------------------------------------------
// Kernel 2: de-serialized epilogue.
// grid = BATCH*8 (w-normalize) + BATCH*2 (ctx reduce) = 320 blocks.
// Data loads are issued BEFORE the inv-sum resolves (independent), so the
// kernel costs one DRAM round-trip, not two chained ones.
// ---------------------------------------------------------------------------
#define WSLICES 8    // SEQ/(NTHREADS*4)

__global__ __launch_bounds__(NTHREADS)
void attn_epilogue(float* __restrict__ ctx_out,   // [BATCH*HID]
                   float* __restrict__ w_out)     // [BATCH*SEQ]
{
    const bool is_ctx = blockIdx.x >= BATCH * WSLICES;
    const int  b      = is_ctx ? ((blockIdx.x - BATCH * WSLICES) >> 1)
                               : (blockIdx.x / WSLICES);
    const int  tid    = threadIdx.x;

    __shared__ float s_inv;

    if (!is_ctx) {
        const int slice = blockIdx.x % WSLICES;
        float4* wp = reinterpret_cast<float4*>(w_out + (size_t)b * SEQ) +
                     slice * NTHREADS;

        // issue the data load FIRST (independent of the sum reduce)
        float4 t = wp[tid];

        if (tid < 32) {
            const float* sp = g_sum_part + b * CHUNKS;
            float v = sp[tid];
            if (tid + 32 < CHUNKS) v += sp[tid + 32];
            #pragma unroll
            for (int off = 16; off; off >>= 1)
                v += __shfl_xor_sync(0xFFFFFFFFu, v, off);
            if (tid == 0) s_inv = __frcp_rn(v);
        }
        __syncthreads();
        const float inv = s_inv;

        t.x *= inv; t.y *= inv; t.z *= inv; t.w *= inv;
        wp[tid] = t;
    } else {
        // ctx reduce: 2 blocks per batch, one h per thread; 37 independent
        // partial loads accumulate while warp 0 reduces the sums in parallel.
        const int h = ((blockIdx.x - BATCH * WSLICES) & 1) * NTHREADS + tid;

        const float* pp = g_ctx_part + (size_t)b * CHUNKS * HID + h;
        float acc = 0.0f;
        #pragma unroll
        for (int c = 0; c < CHUNKS; c++)
            acc += pp[(size_t)c * HID];

        if (tid < 32) {
            const float* sp = g_sum_part + b * CHUNKS;
            float v = sp[tid];
            if (tid + 32 < CHUNKS) v += sp[tid + 32];
            #pragma unroll
            for (int off = 16; off; off >>= 1)
                v += __shfl_xor_sync(0xFFFFFFFFu, v, off);
            if (tid == 0) s_inv = __frcp_rn(v);
        }
        __syncthreads();

        ctx_out[b * HID + h] = acc * s_inv;
    }
}

// ---------------------------------------------------------------------------
extern "C" void kernel_launch(void* const* d_in, const int* in_sizes, int n_in,
                              void* d_out, int out_size)
{
    const float* states_h = nullptr;
    const float* enc_out  = nullptr;
    for (int i = 0; i < n_in; i++) {
        if (in_sizes[i] == BATCH * HID)            states_h = (const float*)d_in[i];
        else if ((int64_t)in_sizes[i] == (int64_t)BATCH * SEQ * HID)
                                                   enc_out  = (const float*)d_in[i];
    }

    float* ctx_out = (float*)d_out;                 // [context | weights]
    float* w_out   = (float*)d_out + BATCH * HID;

    attn_main<<<BATCH * CHUNKS, NTHREADS>>>(states_h, enc_out, w_out);
    attn_epilogue<<<BATCH * WSLICES + BATCH * 2, NTHREADS>>>(ctx_out, w_out);
}